// round 1
// baseline (speedup 1.0000x reference)
#include <cuda_runtime.h>
#include <math.h>

// Shapes (fixed by the problem)
#define B_   8
#define NQ_  1280
#define D_   256
#define CIN_ 64
#define H_   200
#define W_   200

// Scratch (no allocations allowed)
__device__ float g_part[B_][8][D_][4];  // [batch][ci-chunk][out-channel][corner]
__device__ float g_r[B_][D_];           // per-batch residual row

// ---------------------------------------------------------------------------
// K1: 3x3 conv (64->256) evaluated ONLY at the 4 bilinear corner pixels.
// grid = 64 blocks: b = blk>>3, ci-chunk = blk&7 (8 input channels each).
// 256 threads = one output channel each; partial sums to g_part.
// ---------------------------------------------------------------------------
__global__ void k_conv_corners(const float* __restrict__ navi,
                               const float* __restrict__ bev,
                               const float* __restrict__ conv_w) {
    const int b     = blockIdx.x >> 3;
    const int chunk = blockIdx.x & 7;
    const int tid   = threadIdx.x;

    // grid-sample coordinates (same for every query in the batch)
    const float grid_x = navi[2 * b + 1] * (1.0f / 32.0f);
    const float grid_y = navi[2 * b + 0] * (1.0f / 32.0f);
    const float gx = (grid_x + 1.0f) * (0.5f * W_) - 0.5f;
    const float gy = (grid_y + 1.0f) * (0.5f * H_) - 0.5f;
    const int x0 = (int)floorf(gx);
    const int y0 = (int)floorf(gy);

    // 4x4 input patch (union of the 3x3 windows of the 2x2 corner pixels)
    __shared__ float patch[8][16];
    if (tid < 128) {
        const int ci_l = tid >> 4;
        const int pos  = tid & 15;
        const int iy = y0 - 1 + (pos >> 2);
        const int ix = x0 - 1 + (pos & 3);
        const int ci = chunk * 8 + ci_l;
        float v = 0.0f;  // zero padding ('SAME')
        if (iy >= 0 && iy < H_ && ix >= 0 && ix < W_)
            v = bev[((b * CIN_ + ci) * H_ + iy) * W_ + ix];
        patch[ci_l][pos] = v;
    }
    __syncthreads();

    const int co = tid;
    float a0 = 0.f, a1 = 0.f, a2 = 0.f, a3 = 0.f;
    const float* __restrict__ wbase = conv_w + co * (CIN_ * 9) + chunk * (8 * 9);
    #pragma unroll
    for (int cl = 0; cl < 8; cl++) {
        float w[9];
        #pragma unroll
        for (int j = 0; j < 9; j++) w[j] = wbase[cl * 9 + j];
        float p[16];
        #pragma unroll
        for (int j = 0; j < 16; j++) p[j] = patch[cl][j];
        #pragma unroll
        for (int kh = 0; kh < 3; kh++)
            #pragma unroll
            for (int kw = 0; kw < 3; kw++) {
                const float wv = w[kh * 3 + kw];
                a0 = fmaf(wv, p[(kh + 0) * 4 + (kw + 0)], a0);  // (x0,  y0)
                a1 = fmaf(wv, p[(kh + 0) * 4 + (kw + 1)], a1);  // (x0+1,y0)
                a2 = fmaf(wv, p[(kh + 1) * 4 + (kw + 0)], a2);  // (x0,  y0+1)
                a3 = fmaf(wv, p[(kh + 1) * 4 + (kw + 1)], a3);  // (x0+1,y0+1)
            }
    }
    g_part[b][chunk][co][0] = a0;
    g_part[b][chunk][co][1] = a1;
    g_part[b][chunk][co][2] = a2;
    g_part[b][chunk][co][3] = a3;
}

// ---------------------------------------------------------------------------
// K2: per-batch: finish conv (+bias, ReLU), bilinear combine with validity,
// sine-embed score weight (block reduction), then 256x256 GEMV -> g_r.
// grid = 8 blocks (one batch), 256 threads (one out dim each).
// Note: aw = softmax over a size-1 axis = 1.0 exactly; aw_w/aw_b are dead.
// ---------------------------------------------------------------------------
__global__ void k_combine(const float* __restrict__ navi,
                          const float* __restrict__ point_score,
                          const float* __restrict__ aws_w,
                          const float* __restrict__ aws_b,
                          const float* __restrict__ conv_b,
                          const float* __restrict__ out_w,
                          const float* __restrict__ out_b) {
    const int b = blockIdx.x;
    const int d = threadIdx.x;
    __shared__ float s_s[D_];
    __shared__ float red[D_];

    // --- sine embedding of point_score, dotted with aws_w -> per-batch scalar
    // emb[d<128] from point_score[b,1] (y), emb[d>=128] from point_score[b,0] (x)
    const float v = (d < 128) ? point_score[2 * b + 1] : point_score[2 * b + 0];
    const int k = (d & 127) >> 1;
    const float LOG2_10000 = 13.28771237954945f;
    const float inv_t = exp2f(-(float)k * (LOG2_10000 / 64.0f)); // 10000^{-k/64}
    const float arg = v * 6.283185307179586f * inv_t;
    const float e = (d & 1) ? cosf(arg) : sinf(arg);
    red[d] = e * aws_w[d];
    __syncthreads();
    #pragma unroll
    for (int s = 128; s > 0; s >>= 1) {
        if (d < s) red[d] += red[d + s];
        __syncthreads();
    }
    const float aws = red[0] + aws_b[0];

    // --- bilinear weights with zero-padding validity
    const float grid_x = navi[2 * b + 1] * (1.0f / 32.0f);
    const float grid_y = navi[2 * b + 0] * (1.0f / 32.0f);
    const float gx = (grid_x + 1.0f) * (0.5f * W_) - 0.5f;
    const float gy = (grid_y + 1.0f) * (0.5f * H_) - 0.5f;
    const float x0f = floorf(gx), y0f = floorf(gy);
    const float wx1 = gx - x0f, wy1 = gy - y0f;
    const int x0 = (int)x0f, y0 = (int)y0f;
    float wt[4] = { (1.f - wx1) * (1.f - wy1), wx1 * (1.f - wy1),
                    (1.f - wx1) * wy1,         wx1 * wy1 };
    const int ix[4] = { x0, x0 + 1, x0,     x0 + 1 };
    const int iy[4] = { y0, y0,     y0 + 1, y0 + 1 };
    #pragma unroll
    for (int p = 0; p < 4; p++)
        if (!(ix[p] >= 0 && ix[p] < W_ && iy[p] >= 0 && iy[p] < H_)) wt[p] = 0.0f;

    // --- finish conv at the 4 corners, ReLU, sample, scale by aws
    const float cb = conv_b[d];
    float sampled = 0.0f;
    #pragma unroll
    for (int p = 0; p < 4; p++) {
        float sum = 0.0f;
        #pragma unroll
        for (int c = 0; c < 8; c++) sum += g_part[b][c][d][p];
        const float val = fmaxf(sum + cb, 0.0f);
        sampled = fmaf(wt[p], val, sampled);
    }
    s_s[d] = sampled * aws;   // aw == 1 (softmax over 1 element)
    __syncthreads();

    // --- out projection GEMV row: r[d] = out_b[d] + sum_c out_w[d,c]*s[c]
    float r = out_b[d];
    const float* __restrict__ wr = out_w + d * D_;
    #pragma unroll 8
    for (int c = 0; c < D_; c++) r = fmaf(wr[c], s_s[c], r);
    g_r[b][d] = r;
}

// ---------------------------------------------------------------------------
// K3: out[b,q,:] = queries[b,q,:] + r[b,:]   (float4 vectorized stream)
// ---------------------------------------------------------------------------
__global__ void k_bcast_add(const float* __restrict__ q,
                            float* __restrict__ out, int n4) {
    const int i = blockIdx.x * blockDim.x + threadIdx.x;
    if (i >= n4) return;
    float4 a = ((const float4*)q)[i];
    const int b  = i / (NQ_ * (D_ / 4));
    const int d4 = i & (D_ / 4 - 1);
    const float4 rv = __ldg(((const float4*)g_r) + b * (D_ / 4) + d4);
    a.x += rv.x; a.y += rv.y; a.z += rv.z; a.w += rv.w;
    ((float4*)out)[i] = a;
}

// ---------------------------------------------------------------------------
extern "C" void kernel_launch(void* const* d_in, const int* in_sizes, int n_in,
                              void* d_out, int out_size) {
    const float* queries     = (const float*)d_in[0];
    const float* navi        = (const float*)d_in[1];
    const float* bev         = (const float*)d_in[2];
    // d_in[3] spatial_shape (int32) unused: H=W=200 fixed
    const float* point_score = (const float*)d_in[4];
    // d_in[5] aw_w, d_in[6] aw_b: dead (softmax over size-1 axis == 1)
    const float* aws_w       = (const float*)d_in[7];
    const float* aws_b       = (const float*)d_in[8];
    const float* conv_w      = (const float*)d_in[9];
    const float* conv_b      = (const float*)d_in[10];
    const float* out_w       = (const float*)d_in[11];
    const float* out_b       = (const float*)d_in[12];

    k_conv_corners<<<64, 256>>>(navi, bev, conv_w);
    k_combine<<<B_, 256>>>(navi, point_score, aws_w, aws_b, conv_b, out_w, out_b);
    const int n4 = B_ * NQ_ * (D_ / 4);
    k_bcast_add<<<(n4 + 255) / 256, 256>>>(queries, (float*)d_out, n4);
}

// round 2
// speedup vs baseline: 3.1951x; 3.1951x over previous
#include <cuda_runtime.h>
#include <math.h>

// Fixed shapes
#define B_   8
#define NQ_  1280
#define D_   256
#define CIN_ 64
#define H_   200
#define W_   200

// Block roles: [0,64) conv stage A; [64,96) combine+GEMV stage B; [96,256) stream consumers
#define NBLK_A 64
#define NBLK_B 32
#define NCONS  160            // 160 blocks * 256 thr * 16 float4 = 655360 float4 = 8*1280*256 floats
#define NTOT   (NBLK_A + NBLK_B + NCONS)   // 256 blocks, all resident in wave 1

// Scratch + sync (no allocations allowed)
__device__ float g_part[B_][8][D_][4];   // conv partial sums per ci-chunk per corner
__device__ float g_r[B_][D_];            // per-batch residual row
__device__ unsigned int g_flagA;         // = NBLK_A when stage A done
__device__ unsigned int g_flagB;         // = NBLK_B when stage B done
__device__ unsigned int g_done;          // completion counter for flag reset

__global__ __launch_bounds__(256) void fused_kernel(
    const float* __restrict__ queries,
    const float* __restrict__ navi,
    const float* __restrict__ bev,
    const float* __restrict__ point_score,
    const float* __restrict__ aws_w,
    const float* __restrict__ aws_b,
    const float* __restrict__ conv_w,
    const float* __restrict__ conv_b,
    const float* __restrict__ out_w,
    const float* __restrict__ out_b,
    float* __restrict__ out)
{
    const int blk = blockIdx.x;
    const int tid = threadIdx.x;

    if (blk < NBLK_A) {
        // ================= Stage A: 3x3 conv at the 4 bilinear corner pixels ======
        const int b     = blk >> 3;
        const int chunk = blk & 7;   // 8 input channels per chunk

        const float gx = (navi[2*b+1] * (1.0f/32.0f) + 1.0f) * (0.5f * W_) - 0.5f;
        const float gy = (navi[2*b+0] * (1.0f/32.0f) + 1.0f) * (0.5f * H_) - 0.5f;
        const int x0 = (int)floorf(gx);
        const int y0 = (int)floorf(gy);

        __shared__ float patch[8][16];   // 4x4 patch per local input channel
        if (tid < 128) {
            const int ci_l = tid >> 4, pos = tid & 15;
            const int iy = y0 - 1 + (pos >> 2);
            const int ix = x0 - 1 + (pos & 3);
            float v = 0.0f;   // zero padding
            if (iy >= 0 && iy < H_ && ix >= 0 && ix < W_)
                v = bev[((b * CIN_ + chunk * 8 + ci_l) * H_ + iy) * W_ + ix];
            patch[ci_l][pos] = v;
        }

        // Prefetch all 72 weights as 18 batched LDG.128 (high MLP)
        const float4* __restrict__ wv =
            (const float4*)(conv_w + tid * (CIN_ * 9) + chunk * 72);
        float4 wq[18];
        #pragma unroll
        for (int j = 0; j < 18; j++) wq[j] = wv[j];
        const float* w = (const float*)wq;

        __syncthreads();

        float a0 = 0.f, a1 = 0.f, a2 = 0.f, a3 = 0.f;
        #pragma unroll
        for (int cl = 0; cl < 8; cl++) {
            float p[16];
            #pragma unroll
            for (int j = 0; j < 16; j++) p[j] = patch[cl][j];
            const float* wc = w + cl * 9;
            #pragma unroll
            for (int kh = 0; kh < 3; kh++)
                #pragma unroll
                for (int kw = 0; kw < 3; kw++) {
                    const float wvv = wc[kh * 3 + kw];
                    a0 = fmaf(wvv, p[(kh + 0) * 4 + (kw + 0)], a0);
                    a1 = fmaf(wvv, p[(kh + 0) * 4 + (kw + 1)], a1);
                    a2 = fmaf(wvv, p[(kh + 1) * 4 + (kw + 0)], a2);
                    a3 = fmaf(wvv, p[(kh + 1) * 4 + (kw + 1)], a3);
                }
        }
        *(float4*)&g_part[b][chunk][tid][0] = make_float4(a0, a1, a2, a3);
        __threadfence();
        __syncthreads();
        if (tid == 0) atomicAdd(&g_flagA, 1);

    } else if (blk < NBLK_A + NBLK_B) {
        // ================= Stage B: bias+ReLU+bilinear+aws, then 256x256 GEMV =====
        const int blkB  = blk - NBLK_A;
        const int b     = blkB >> 2;            // batch
        const int rg    = blkB & 3;             // row-group (64 rows of out_w)
        const int row_l = tid >> 2;             // 0..63
        const int qq    = tid & 3;              // column quarter (64 cols)
        const int d     = rg * 64 + row_l;      // output row 0..255

        // Prefetch this thread's out_w segment BEFORE spinning (hides cold DRAM)
        const float4* __restrict__ wp = (const float4*)(out_w + d * D_ + qq * 64);
        float4 wreg[16];
        #pragma unroll
        for (int j = 0; j < 16; j++) wreg[j] = wp[j];
        const float ob = out_b[d];

        // Pre-spin: per-channel (c = tid) sine-embed term, conv bias, bilinear wts
        const int c = tid;
        const float v = (c < 128) ? point_score[2*b+1] : point_score[2*b+0];
        const int kk = (c & 127) >> 1;
        const float inv_t = exp2f(-(float)kk * (13.28771237954945f / 64.0f)); // 10000^{-kk/64}
        const float arg = v * 6.283185307179586f * inv_t;
        const float e = (c & 1) ? cosf(arg) : sinf(arg);
        const float awsterm = e * aws_w[c];
        const float awsbias = aws_b[0];
        const float cb = conv_b[c];

        const float gx = (navi[2*b+1] * (1.0f/32.0f) + 1.0f) * (0.5f * W_) - 0.5f;
        const float gy = (navi[2*b+0] * (1.0f/32.0f) + 1.0f) * (0.5f * H_) - 0.5f;
        const float x0f = floorf(gx), y0f = floorf(gy);
        const float wx1 = gx - x0f, wy1 = gy - y0f;
        const int x0 = (int)x0f, y0 = (int)y0f;
        float wt0 = (1.f - wx1) * (1.f - wy1);
        float wt1 = wx1 * (1.f - wy1);
        float wt2 = (1.f - wx1) * wy1;
        float wt3 = wx1 * wy1;
        const bool vx0 = (x0 >= 0 && x0 < W_), vx1 = (x0+1 >= 0 && x0+1 < W_);
        const bool vy0 = (y0 >= 0 && y0 < H_), vy1 = (y0+1 >= 0 && y0+1 < H_);
        if (!(vx0 && vy0)) wt0 = 0.f;
        if (!(vx1 && vy0)) wt1 = 0.f;
        if (!(vx0 && vy1)) wt2 = 0.f;
        if (!(vx1 && vy1)) wt3 = 0.f;

        __shared__ float red[D_];
        __shared__ float s_s[D_];
        __shared__ float s_part[D_];

        // Wait for conv partials
        if (tid == 0) {
            while (atomicAdd(&g_flagA, 0) < NBLK_A) __nanosleep(40);
        }
        __syncthreads();

        // aws = sineembed(point_score) . aws_w + aws_b  (block reduction)
        red[tid] = awsterm;
        __syncthreads();
        #pragma unroll
        for (int s = 128; s > 0; s >>= 1) {
            if (tid < s) red[tid] += red[tid + s];
            __syncthreads();
        }
        const float aws = red[0] + awsbias;

        // finish conv at 4 corners (+bias, ReLU), bilinear combine, scale by aws
        float4 acc = make_float4(0.f, 0.f, 0.f, 0.f);
        #pragma unroll
        for (int ch = 0; ch < 8; ch++) {
            const float4 pp = *(const float4*)&g_part[b][ch][c][0];
            acc.x += pp.x; acc.y += pp.y; acc.z += pp.z; acc.w += pp.w;
        }
        const float v0 = fmaxf(acc.x + cb, 0.f);
        const float v1 = fmaxf(acc.y + cb, 0.f);
        const float v2 = fmaxf(acc.z + cb, 0.f);
        const float v3 = fmaxf(acc.w + cb, 0.f);
        s_s[c] = (wt0 * v0 + wt1 * v1 + wt2 * v2 + wt3 * v3) * aws;  // aw == 1
        __syncthreads();

        // GEMV quarter-row from preloaded registers
        const float* sseg = s_s + qq * 64;
        const float* wr = (const float*)wreg;
        float part = 0.f;
        #pragma unroll
        for (int j = 0; j < 64; j++) part = fmaf(wr[j], sseg[j], part);
        s_part[tid] = part;
        __syncthreads();
        if (qq == 0)
            g_r[b][d] = ob + s_part[tid] + s_part[tid+1] + s_part[tid+2] + s_part[tid+3];
        __threadfence();
        __syncthreads();
        if (tid == 0) atomicAdd(&g_flagB, 1);

    } else {
        // ================= Consumers: out = queries + r[b]  (prefetch then add) ===
        const int base = (blk - NBLK_A - NBLK_B) * 4096 + tid;  // float4 index
        const float4* __restrict__ q4 = (const float4*)queries;
        float4* __restrict__ o4 = (float4*)out;

        // Prefetch 16 float4 (streams the whole 10.5MB read during stages A/B)
        float4 a[16];
        #pragma unroll
        for (int k = 0; k < 16; k++) a[k] = q4[base + k * 256];

        if (tid == 0) {
            while (atomicAdd(&g_flagB, 0) < NBLK_B) __nanosleep(40);
        }
        __syncthreads();

        const int d4 = base & 63;   // same for all k (stride 256 preserves mod 64)
        const float4* __restrict__ r4 = (const float4*)g_r;
        #pragma unroll
        for (int k = 0; k < 16; k++) {
            const int idx = base + k * 256;
            const int bb = idx / (NQ_ * (D_ / 4));   // idx / 81920
            const float4 rv = r4[bb * (D_ / 4) + d4];
            float4 t = a[k];
            t.x += rv.x; t.y += rv.y; t.z += rv.z; t.w += rv.w;
            o4[idx] = t;
        }
    }

    // ---- flag reset by the last block to finish (keeps replays deterministic) ----
    __syncthreads();
    if (tid == 0) {
        const unsigned int t = atomicAdd(&g_done, 1);
        if (t == NTOT - 1) {
            g_done  = 0;
            g_flagA = 0;
            g_flagB = 0;
        }
    }
}

extern "C" void kernel_launch(void* const* d_in, const int* in_sizes, int n_in,
                              void* d_out, int out_size) {
    const float* queries     = (const float*)d_in[0];
    const float* navi        = (const float*)d_in[1];
    const float* bev         = (const float*)d_in[2];
    // d_in[3] spatial_shape unused (H=W=200 fixed)
    const float* point_score = (const float*)d_in[4];
    // d_in[5] aw_w, d_in[6] aw_b dead: softmax over size-1 axis == 1
    const float* aws_w       = (const float*)d_in[7];
    const float* aws_b       = (const float*)d_in[8];
    const float* conv_w      = (const float*)d_in[9];
    const float* conv_b      = (const float*)d_in[10];
    const float* out_w       = (const float*)d_in[11];
    const float* out_b       = (const float*)d_in[12];

    fused_kernel<<<NTOT, 256>>>(queries, navi, bev, point_score,
                                aws_w, aws_b, conv_w, conv_b,
                                out_w, out_b, (float*)d_out);
}